// round 2
// baseline (speedup 1.0000x reference)
#include <cuda_runtime.h>
#include <cstdint>

#define NQ     8
#define DIM    256
#define NW     16
#define BATCH  16
#define NCIRC  256     /* BATCH * NW */
#define NROTS  64
#define EMB    512
#define VOCAB  50257
#define NM     24

typedef unsigned long long ull;

/* ---------------- scratch (device globals; no allocation allowed) -------- */
__device__ float2 g_coeffs[NW];
__device__ float  g_wparams[NCIRC * NROTS];
__device__ float2 g_work[BATCH * DIM];
__device__ float2 g_st[NCIRC * DIM];
__device__ float2 g_acc[BATCH * DIM];
__device__ float  g_fp[BATCH];
__device__ float  g_h[BATCH * EMB];

/* ---------------- packed f32x2 helpers ----------------------------------- */
__device__ __forceinline__ ull fma2(ull a, ull b, ull c) {
    ull d;
    asm("fma.rn.f32x2 %0, %1, %2, %3;" : "=l"(d) : "l"(a), "l"(b), "l"(c));
    return d;
}
__device__ __forceinline__ float2 upk2(ull v) {
    float lo, hi;
    asm("mov.b64 {%0, %1}, %2;" : "=f"(lo), "=f"(hi) : "l"(v));
    return make_float2(lo, hi);
}

/* ---------------- gate machinery ----------------------------------------- */
/* qubit q -> bit position (NQ-1-q). Params are consumed in program order:
   per layer: 8 RY (q=0..7), 8 CRX (ctrl=7..0, tgt=(c+1)%8),
              8 RY (q=0..7), 8 CRX (ctrl in [7,0,1..6], tgt=(c-1)%8).       */
__device__ __forceinline__ void apply_gates(float2* st, const float2* cs,
                                            int tid, int ngates) {
    for (int g = 0; g < ngates; g++) {
        int gl = g & 31;
        float c = cs[g].x, s = cs[g].y;
        if ((gl & 8) == 0) {                       /* RY on qubit q */
            int q  = gl & 7;
            int bp = 7 - q;
            int ml = (1 << bp) - 1;
            int i0 = ((tid & ~ml) << 1) | (tid & ml);
            int i1 = i0 | (1 << bp);
            float2 a0 = st[i0], a1 = st[i1];
            st[i0] = make_float2(c * a0.x - s * a1.x, c * a0.y - s * a1.y);
            st[i1] = make_float2(s * a0.x + c * a1.x, s * a0.y + c * a1.y);
        } else if (tid < 64) {                     /* CRX(ctrl, tgt) */
            int j = gl & 7;
            int ctrl, tgt;
            if (gl < 16) { ctrl = 7 - j;                 tgt = (ctrl + 1) & 7; }
            else         { ctrl = (j == 0) ? 7 : (j - 1); tgt = (ctrl + 7) & 7; }
            int bc = 7 - ctrl, bt = 7 - tgt;
            int lo = bc < bt ? bc : bt;
            int hi = bc < bt ? bt : bc;
            int mlo = (1 << lo) - 1, mhi = (1 << hi) - 1;
            int m = tid;
            m = ((m & ~mlo) << 1) | (m & mlo);     /* insert 0 at lo */
            m = ((m & ~mhi) << 1) | (m & mhi);     /* insert 0 at hi */
            int i0 = m | (1 << bc);                /* control bit = 1 */
            int i1 = i0 | (1 << bt);
            float2 a0 = st[i0], a1 = st[i1];
            /* RX: a0' = c a0 - i s a1 ; a1' = -i s a0 + c a1 */
            st[i0] = make_float2(c * a0.x + s * a1.y, c * a0.y - s * a1.x);
            st[i1] = make_float2(s * a0.y + c * a1.x, -s * a0.x + c * a1.y);
        }
        __syncthreads();
    }
}

/* ---------------- kernel 0: coeffs + work/acc init ----------------------- */
__global__ void k_setup(const float* __restrict__ mix,
                        const float* __restrict__ poly) {
    int tid = threadIdx.x;
    if (tid == 0) {
        float s = 0.f;
        for (int w = 0; w < NW; w++)
            s += sqrtf(mix[2 * w] * mix[2 * w] + mix[2 * w + 1] * mix[2 * w + 1]);
        float inv = 1.0f / fmaxf(s, 1e-12f);
        for (int w = 0; w < NW; w++)
            g_coeffs[w] = make_float2(mix[2 * w] * inv, mix[2 * w + 1] * inv);
    }
    float p0 = poly[0];
    for (int idx = tid; idx < BATCH * DIM; idx += blockDim.x) {
        bool z = (idx & (DIM - 1)) == 0;
        g_work[idx] = z ? make_float2(1.f, 0.f) : make_float2(0.f, 0.f);
        g_acc[idx]  = z ? make_float2(p0, 0.f)  : make_float2(0.f, 0.f);
    }
}

/* ---------------- kernel 1: wparams = emb @ e2rW^T + b ------------------- */
__global__ void k_wparams(const int* __restrict__ x,
                          const float* __restrict__ embW,
                          const float* __restrict__ e2rW,
                          const float* __restrict__ e2rb) {
    int bw = blockIdx.x, tid = threadIdx.x;      /* 64 threads */
    __shared__ float emb[EMB];
    int tok = x[bw];
    for (int k = tid; k < EMB; k += 64)
        emb[k] = embW[(size_t)tok * EMB + k];
    __syncthreads();
    const float4* wr = reinterpret_cast<const float4*>(e2rW + (size_t)tid * EMB);
    const float4* es = reinterpret_cast<const float4*>(emb);
    float acc = e2rb[tid];
#pragma unroll 8
    for (int kk = 0; kk < EMB / 4; kk++) {
        float4 a = wr[kk], b = es[kk];
        acc += a.x * b.x + a.y * b.y + a.z * b.z + a.w * b.w;
    }
    g_wparams[bw * 64 + tid] = acc;
}

/* ---------------- kernel 2: per-circuit 64-gate simulation --------------- */
__global__ void k_sim() {
    int bw = blockIdx.x, tid = threadIdx.x;      /* 128 threads */
    int b  = bw >> 4;
    __shared__ float2 st[DIM];
    __shared__ float2 cs[64];
    st[tid]       = g_work[b * DIM + tid];
    st[tid + 128] = g_work[b * DIM + tid + 128];
    if (tid < 64) {
        float p = g_wparams[bw * 64 + tid];
        cs[tid] = make_float2(cosf(0.5f * p), sinf(0.5f * p));
    }
    __syncthreads();
    apply_gates(st, cs, tid, 64);
    g_st[bw * DIM + tid]       = st[tid];
    g_st[bw * DIM + tid + 128] = st[tid + 128];
}

/* ---------------- kernel 3: word-mix reduce + poly accumulate ------------ */
__global__ void k_reduce(const float* __restrict__ poly, int d) {
    int b = blockIdx.x, i = threadIdx.x;         /* 256 threads */
    float2 s = make_float2(0.f, 0.f);
#pragma unroll
    for (int w = 0; w < NW; w++) {
        float2 cw = g_coeffs[w];
        float2 v  = g_st[(b * NW + w) * DIM + i];
        s.x += cw.x * v.x - cw.y * v.y;
        s.y += cw.x * v.y + cw.y * v.x;
    }
    g_work[b * DIM + i] = s;
    float pd = poly[d];
    float2 a = g_acc[b * DIM + i];
    a.x += pd * s.x; a.y += pd * s.y;
    g_acc[b * DIM + i] = a;
}

/* ------- kernel 4: normalize + final 32-gate sim + measure + FF1 --------- */
__global__ void k_finalize(const float* __restrict__ poly,
                           const float* __restrict__ qff,
                           const float* __restrict__ ff1W,
                           const float* __restrict__ ff1b) {
    int b = blockIdx.x, tid = threadIdx.x;       /* 128 threads */
    __shared__ float2 st[DIM];
    __shared__ float2 cs[32];
    __shared__ float  red[128];
    __shared__ float3 wred[4];
    __shared__ float  e[NM];

    float psum = fabsf(poly[0]) + fabsf(poly[1]) + fabsf(poly[2]) + fabsf(poly[3]);
    float inv1 = 1.0f / psum;
    float2 a0 = g_acc[b * DIM + tid];
    float2 a1 = g_acc[b * DIM + tid + 128];
    a0.x *= inv1; a0.y *= inv1; a1.x *= inv1; a1.y *= inv1;
    red[tid] = a0.x * a0.x + a0.y * a0.y + a1.x * a1.x + a1.y * a1.y;
    __syncthreads();
    for (int s2 = 64; s2 > 0; s2 >>= 1) {
        if (tid < s2) red[tid] += red[tid + s2];
        __syncthreads();
    }
    float nrm = sqrtf(red[0]);
    if (tid == 0) g_fp[b] = nrm;
    float inv2 = 1.0f / fmaxf(nrm, 1e-12f);
    st[tid]       = make_float2(a0.x * inv2, a0.y * inv2);
    st[tid + 128] = make_float2(a1.x * inv2, a1.y * inv2);
    if (tid < 32) {
        float p = qff[tid];
        cs[tid] = make_float2(cosf(0.5f * p), sinf(0.5f * p));
    }
    __syncthreads();
    apply_gates(st, cs, tid, 32);

    int lane = tid & 31, wrp = tid >> 5;
    for (int w = 0; w < NQ; w++) {
        int bp = 7 - w;
        int ml = (1 << bp) - 1;
        int i0 = ((tid & ~ml) << 1) | (tid & ml);
        int i1 = i0 | (1 << bp);
        float2 p0 = st[i0], p1 = st[i1];
        float cre = p0.x * p1.x + p0.y * p1.y;
        float cim = p0.x * p1.y - p0.y * p1.x;
        float zz  = p0.x * p0.x + p0.y * p0.y - p1.x * p1.x - p1.y * p1.y;
        for (int off = 16; off; off >>= 1) {
            cre += __shfl_xor_sync(0xffffffffu, cre, off);
            cim += __shfl_xor_sync(0xffffffffu, cim, off);
            zz  += __shfl_xor_sync(0xffffffffu, zz, off);
        }
        if (lane == 0) wred[wrp] = make_float3(cre, cim, zz);
        __syncthreads();
        if (tid == 0) {
            float sr = 0.f, si = 0.f, sz = 0.f;
            for (int k = 0; k < 4; k++) { sr += wred[k].x; si += wred[k].y; sz += wred[k].z; }
            e[w] = 2.f * sr; e[8 + w] = 2.f * si; e[16 + w] = sz;
        }
        __syncthreads();
    }

    for (int j = tid; j < EMB; j += 128) {
        float s = ff1b[j];
#pragma unroll
        for (int m = 0; m < NM; m++) s += e[m] * ff1W[j * NM + m];
        g_h[b * EMB + j] = fmaxf(s, 0.f);
    }
}

/* ---------------- kernel 5: mean of final_probs -------------------------- */
__global__ void k_mean(float* __restrict__ out) {
    float s = 0.f;
    for (int b = 0; b < BATCH; b++) s += g_fp[b];
    out[(size_t)BATCH * VOCAB] = s * (1.0f / BATCH);
}

/* ---------- kernel 6: op = h @ ff2W^T + b  (HBM-bound; f32x2 FMA) -------- */
__global__ void __launch_bounds__(128) k_ff2(const float* __restrict__ ff2W,
                                             const float* __restrict__ ff2b,
                                             float* __restrict__ out) {
    /* hs2[kp][b] = packed (h[b][2kp], h[b][2kp+1]) : 256*16 ull = 32 KB */
    __shared__ ull hs2[256 * 16];
    int tid = threadIdx.x;
    for (int idx = tid; idx < 256 * 16; idx += 128) {
        int kp = idx >> 4, b = idx & 15;
        float2 hv = *reinterpret_cast<const float2*>(&g_h[b * EMB + 2 * kp]);
        reinterpret_cast<float2*>(hs2)[idx] = hv;
    }
    __syncthreads();

    int v0 = blockIdx.x * 256 + tid;
    int v1 = v0 + 128;
    bool ok0 = v0 < VOCAB, ok1 = v1 < VOCAB;
    const ulonglong2* w0p =
        reinterpret_cast<const ulonglong2*>(ff2W + (size_t)(ok0 ? v0 : 0) * EMB);
    const ulonglong2* w1p =
        reinterpret_cast<const ulonglong2*>(ff2W + (size_t)(ok1 ? v1 : 0) * EMB);

    ull acc0[16], acc1[16];
#pragma unroll
    for (int b = 0; b < 16; b++) { acc0[b] = 0ull; acc1[b] = 0ull; }

    for (int ki = 0; ki < 128; ki++) {           /* 4 k per iter (2 pairs) */
        ulonglong2 wa = w0p[ki];
        ulonglong2 wb = w1p[ki];
        const ull* h0 = &hs2[(ki * 2) * 16];
        const ull* h1 = h0 + 16;
#pragma unroll
        for (int b = 0; b < 16; b += 2) {
            ulonglong2 hb0 = *reinterpret_cast<const ulonglong2*>(h0 + b);
            ulonglong2 hb1 = *reinterpret_cast<const ulonglong2*>(h1 + b);
            acc0[b]     = fma2(wa.x, hb0.x, acc0[b]);
            acc0[b + 1] = fma2(wa.x, hb0.y, acc0[b + 1]);
            acc0[b]     = fma2(wa.y, hb1.x, acc0[b]);
            acc0[b + 1] = fma2(wa.y, hb1.y, acc0[b + 1]);
            acc1[b]     = fma2(wb.x, hb0.x, acc1[b]);
            acc1[b + 1] = fma2(wb.x, hb0.y, acc1[b + 1]);
            acc1[b]     = fma2(wb.y, hb1.x, acc1[b]);
            acc1[b + 1] = fma2(wb.y, hb1.y, acc1[b + 1]);
        }
    }

    float bias0 = ok0 ? ff2b[v0] : 0.f;
    float bias1 = ok1 ? ff2b[v1] : 0.f;
#pragma unroll
    for (int b = 0; b < 16; b++) {
        float2 p = upk2(acc0[b]);
        if (ok0) out[(size_t)b * VOCAB + v0] = p.x + p.y + bias0;
        float2 q = upk2(acc1[b]);
        if (ok1) out[(size_t)b * VOCAB + v1] = q.x + q.y + bias1;
    }
}

/* ---------------- launch ------------------------------------------------- */
extern "C" void kernel_launch(void* const* d_in, const int* in_sizes, int n_in,
                              void* d_out, int out_size) {
    const int*   x    = (const int*)  d_in[0];
    const float* embW = (const float*)d_in[1];
    const float* e2rW = (const float*)d_in[2];
    const float* e2rb = (const float*)d_in[3];
    const float* poly = (const float*)d_in[4];
    const float* mix  = (const float*)d_in[5];
    const float* qff  = (const float*)d_in[6];
    const float* ff1W = (const float*)d_in[7];
    const float* ff1b = (const float*)d_in[8];
    const float* ff2W = (const float*)d_in[9];
    const float* ff2b = (const float*)d_in[10];
    float* out = (float*)d_out;

    k_setup<<<1, 256>>>(mix, poly);
    k_wparams<<<NCIRC, 64>>>(x, embW, e2rW, e2rb);
    for (int d = 1; d <= 3; d++) {
        k_sim<<<NCIRC, 128>>>();
        k_reduce<<<BATCH, 256>>>(poly, d);
    }
    k_finalize<<<BATCH, 128>>>(poly, qff, ff1W, ff1b);
    if (out_size > BATCH * VOCAB) k_mean<<<1, 1>>>(out);
    k_ff2<<<(VOCAB + 255) / 256, 128>>>(ff2W, ff2b, out);
}